// round 12
// baseline (speedup 1.0000x reference)
#include <cuda_runtime.h>
#include <cuda_bf16.h>
#include <cuda_fp16.h>

// 3D LUT trilinear interpolation.
// x:   [8, 3, 1920, 1080] f32
// lut: [3, 33, 33, 33]    f32  (indexed [chan, b, g, r], r fastest)
// out: [8, 3, 1920, 1080] f32  (same layout as x)
//
// R11: per-warp modulo-scheduled pipeline at 768 threads (reg cap 85 vs 64
// at 1024 -> room for two gather generations in flight without spilling).
// Steady state per iteration, processing group i:
//   1. prefetch x(i+2)            (LDG latency spans 2 iterations)
//   2. fidx + gathers for (i+1)   (LDS latency spans 1 iteration)
//   3. lerp + store group i       (consumes w_cur/fr_cur from last iter)
// Keeps: persistent 148-CTA single wave, 1 channel/CTA (bid%3), fp16 r-pair
// table 139KB smem, exact magic-number floor.

#define NPLANE   (1920 * 1080)
#define NBATCH   8
#define NPIX     (NBATCH * NPLANE)    // 16,588,800
#define LUTC     35937                // 33^3
#define PACKN    (33 * 33 * 32)       // 34,848 packed half2 entries
#define G_STRIDE 32
#define B_STRIDE (33 * 32)            // 1056
#define THREADS  768
#define NCTA     148
#define SMEM_BYTES (PACKN * 4)        // 139,392 B

__device__ __forceinline__ void fidx(float v, float invbin, int& i, float& fr) {
    float xv = v * invbin;
    float t  = fmaf(v, invbin, -0.5f);          // in [-0.5, 31.5)
    float f  = t + 12582912.0f;                 // int part = floor(xv)
    i  = __float_as_int(f) - 0x4B400000;
    fr = xv - (f - 12582912.0f);
}

// Load one group's x (3 coalesced float4).
__device__ __forceinline__ void load_x(const float* __restrict__ x, int gidx,
                                       float4& r4, float4& g4, float4& b4) {
    int q    = gidx * 4;
    int bimg = q / NPLANE;
    int p    = q - bimg * NPLANE;
    const float* xb = x + (size_t)bimg * 3 * NPLANE + p;
    r4 = *(const float4*)(xb);
    g4 = *(const float4*)(xb + NPLANE);
    b4 = *(const float4*)(xb + 2 * NPLANE);
}

// Indices+fracs for 4 pixels, then issue all 16 gathers.
__device__ __forceinline__ void stage_gather(const unsigned* __restrict__ slut2,
                                             float4 r4, float4 g4, float4 b4,
                                             float invbin,
                                             unsigned w[16], float fr[12]) {
    float rv[4] = {r4.x, r4.y, r4.z, r4.w};
    float gv[4] = {g4.x, g4.y, g4.z, g4.w};
    float bv[4] = {b4.x, b4.y, b4.z, b4.w};
    #pragma unroll
    for (int k = 0; k < 4; k++) {
        int ir, ig, ib;
        fidx(rv[k], invbin, ir, fr[k]);
        fidx(gv[k], invbin, ig, fr[4 + k]);
        fidx(bv[k], invbin, ib, fr[8 + k]);
        int base = ib * B_STRIDE + ig * G_STRIDE + ir;
        w[4*k + 0] = slut2[base];
        w[4*k + 1] = slut2[base + G_STRIDE];
        w[4*k + 2] = slut2[base + B_STRIDE];
        w[4*k + 3] = slut2[base + B_STRIDE + G_STRIDE];
    }
}

// Lerp 4 pixels from gathered words and store one float4.
__device__ __forceinline__ void stage_lerp_store(float* __restrict__ out,
                                                 int gidx, int chan,
                                                 const unsigned w[16],
                                                 const float fr[12]) {
    float o[4];
    #pragma unroll
    for (int k = 0; k < 4; k++) {
        float2 f00 = __half22float2(*(const __half2*)&w[4*k + 0]);
        float2 f01 = __half22float2(*(const __half2*)&w[4*k + 1]);
        float2 f10 = __half22float2(*(const __half2*)&w[4*k + 2]);
        float2 f11 = __half22float2(*(const __half2*)&w[4*k + 3]);
        float c00 = fmaf(fr[k], f00.y - f00.x, f00.x);
        float c01 = fmaf(fr[k], f01.y - f01.x, f01.x);
        float c10 = fmaf(fr[k], f10.y - f10.x, f10.x);
        float c11 = fmaf(fr[k], f11.y - f11.x, f11.x);
        float c0  = fmaf(fr[4 + k], c01 - c00, c00);
        float c1  = fmaf(fr[4 + k], c11 - c10, c10);
        o[k] = fmaf(fr[8 + k], c1 - c0, c0);
    }
    int q    = gidx * 4;
    int bimg = q / NPLANE;
    int p    = q - bimg * NPLANE;
    *(float4*)(out + (size_t)bimg * 3 * NPLANE + (size_t)chan * NPLANE + p)
        = make_float4(o[0], o[1], o[2], o[3]);
}

__global__ void __launch_bounds__(THREADS, 1)
lut3d_kernel(const float* __restrict__ lut,
             const float* __restrict__ x,
             float* __restrict__ out) {
    extern __shared__ unsigned slut2[];

    const int chan  = blockIdx.x % 3;
    const int cid   = blockIdx.x / 3;
    const int nchan = (NCTA - chan + 2) / 3;    // 50/49/49

    // Build packed half2 table: slut2[(ib*33+ig)*32 + ir] = (v[r], v[r+1]).
    const float* __restrict__ lc = lut + chan * LUTC;
    for (int i = threadIdx.x; i < PACKN; i += THREADS) {
        int ir   = i & 31;
        int rest = i >> 5;
        int src  = rest * 33 + ir;
        __half2 h = __floats2half2_rn(lc[src], lc[src + 1]);
        slut2[i] = *(const unsigned*)&h;
    }
    __syncthreads();

    const float invbin = 32.0f / 1.000001f;

    const int ngroups = NPIX / 4;
    const int per     = (ngroups + nchan - 1) / nchan;
    const int gbeg    = cid * per;
    const int gend    = min(gbeg + per, ngroups);

    int cur = gbeg + (int)threadIdx.x;
    if (cur >= gend) return;

    // ── Pipeline prologue ──
    float4 r4, g4, b4;
    load_x(x, cur, r4, g4, b4);

    unsigned w_cur[16];
    float    fr_cur[12];
    stage_gather(slut2, r4, g4, b4, invbin, w_cur, fr_cur);

    int nxt = cur + THREADS;
    bool has_nxt = nxt < gend;
    float4 xr, xg, xbv;                 // x for group (i+1)
    if (has_nxt) load_x(x, nxt, xr, xg, xbv);

    // ── Steady state ──
    for (;;) {
        // 1. prefetch x(i+2)
        int pf = nxt + THREADS;
        bool has_pf = has_nxt && (pf < gend);
        float4 pr, pg, pb;
        if (has_pf) load_x(x, pf, pr, pg, pb);

        // 2. fidx + gathers for (i+1)
        unsigned w_nxt[16];
        float    fr_nxt[12];
        if (has_nxt)
            stage_gather(slut2, xr, xg, xbv, invbin, w_nxt, fr_nxt);

        // 3. lerp + store group i
        stage_lerp_store(out, cur, chan, w_cur, fr_cur);

        if (!has_nxt) break;

        // rotate
        cur = nxt; nxt = pf; has_nxt = has_pf;
        xr = pr; xg = pg; xbv = pb;
        #pragma unroll
        for (int j = 0; j < 16; j++) w_cur[j] = w_nxt[j];
        #pragma unroll
        for (int j = 0; j < 12; j++) fr_cur[j] = fr_nxt[j];
    }
}

extern "C" void kernel_launch(void* const* d_in, const int* in_sizes, int n_in,
                              void* d_out, int out_size) {
    const float* lut = (const float*)d_in[0];
    const float* x   = (const float*)d_in[1];
    float* out       = (float*)d_out;

    cudaFuncSetAttribute(lut3d_kernel,
                         cudaFuncAttributeMaxDynamicSharedMemorySize,
                         SMEM_BYTES);
    lut3d_kernel<<<NCTA, THREADS, SMEM_BYTES>>>(lut, x, out);
}

// round 13
// speedup vs baseline: 1.2261x; 1.2261x over previous
#include <cuda_runtime.h>
#include <cuda_bf16.h>
#include <cuda_fp16.h>

// 3D LUT trilinear interpolation.
// x:   [8, 3, 1920, 1080] f32
// lut: [3, 33, 33, 33]    f32  (indexed [chan, b, g, r], r fastest)
// out: [8, 3, 1920, 1080] f32  (same layout as x)
//
// R12: revert to R10 structure (1024 thr, 32 warps/SM — R11 proved cross-warp
// TLP beats per-warp pipelining here). Strength-reduce addressing: carry
// (p, bimg) incrementally (stride 4096 < NPLANE -> single conditional wrap)
// instead of two integer divisions per iteration; prefetch coords rotate into
// current. Keeps: persistent 148-CTA single wave, 1 channel/CTA (bid%3),
// fp16 r-pair table (139KB smem), exact magic-number floor, x prefetch.

#define NPLANE   (1920 * 1080)        // 2,073,600
#define NBATCH   8
#define NPIX     (NBATCH * NPLANE)    // 16,588,800
#define LUTC     35937                // 33^3
#define PACKN    (33 * 33 * 32)       // 34,848 packed half2 entries
#define G_STRIDE 32
#define B_STRIDE (33 * 32)            // 1056
#define THREADS  1024
#define NCTA     148
#define STRIDEPX (THREADS * 4)        // 4096 pixels per thread-step
#define SMEM_BYTES (PACKN * 4)        // 139,392 B

// floor+frac for xv = v*invbin in [0, 32): exact, no cvt-pipe ops.
__device__ __forceinline__ void fidx(float v, float invbin, int& i, float& fr) {
    float xv = v * invbin;
    float t  = fmaf(v, invbin, -0.5f);          // in [-0.5, 31.5)
    float f  = t + 12582912.0f;                 // int part = floor(xv)
    i  = __float_as_int(f) - 0x4B400000;
    fr = xv - (f - 12582912.0f);
}

__global__ void __launch_bounds__(THREADS, 1)
lut3d_kernel(const float* __restrict__ lut,
             const float* __restrict__ x,
             float* __restrict__ out) {
    extern __shared__ unsigned slut2[];

    const int chan  = blockIdx.x % 3;
    const int cid   = blockIdx.x / 3;
    const int nchan = (NCTA - chan + 2) / 3;    // 50/49/49

    // Build packed half2 table: slut2[(ib*33+ig)*32 + ir] = (v[r], v[r+1]).
    const float* __restrict__ lc = lut + chan * LUTC;
    for (int i = threadIdx.x; i < PACKN; i += THREADS) {
        int ir   = i & 31;
        int rest = i >> 5;
        int src  = rest * 33 + ir;
        __half2 h = __floats2half2_rn(lc[src], lc[src + 1]);
        slut2[i] = *(const unsigned*)&h;
    }
    __syncthreads();

    const float invbin = 32.0f / 1.000001f;

    const int ngroups = NPIX / 4;
    const int per     = (ngroups + nchan - 1) / nchan;
    const int gbeg    = cid * per;
    const int gend    = min(gbeg + per, ngroups);

    int gidx = gbeg + (int)threadIdx.x;
    if (gidx >= gend) return;

    float* __restrict__ outc = out + (size_t)chan * NPLANE;   // + bimg*3*NPLANE + p

    // Coordinates of current group (single division here, incremental after).
    int q    = gidx * 4;
    int bimg = q / NPLANE;
    int p    = q - bimg * NPLANE;

    const float* xb = x + (size_t)bimg * 3 * NPLANE + p;
    float4 r4 = *(const float4*)(xb);
    float4 g4 = *(const float4*)(xb + NPLANE);
    float4 b4 = *(const float4*)(xb + 2 * NPLANE);

    for (;;) {
        // Phase 1: indices + fracs for all 4 pixels.
        float rv[4] = {r4.x, r4.y, r4.z, r4.w};
        float gv[4] = {g4.x, g4.y, g4.z, g4.w};
        float bv[4] = {b4.x, b4.y, b4.z, b4.w};
        int   base[4];
        float rd[4], gd[4], bd[4];
        #pragma unroll
        for (int k = 0; k < 4; k++) {
            int ir, ig, ib;
            fidx(rv[k], invbin, ir, rd[k]);
            fidx(gv[k], invbin, ig, gd[k]);
            fidx(bv[k], invbin, ib, bd[k]);
            base[k] = ib * B_STRIDE + ig * G_STRIDE + ir;
        }

        // Phase 2: all 16 gathers back-to-back.
        unsigned w[16];
        #pragma unroll
        for (int k = 0; k < 4; k++) {
            w[4*k + 0] = slut2[base[k]];
            w[4*k + 1] = slut2[base[k] + G_STRIDE];
            w[4*k + 2] = slut2[base[k] + B_STRIDE];
            w[4*k + 3] = slut2[base[k] + B_STRIDE + G_STRIDE];
        }

        // Phase 3: next-group coords (incremental wrap) + x prefetch.
        const int ngidx = gidx + THREADS;
        const bool has_next = ngidx < gend;
        int np    = p + STRIDEPX;
        int nbimg = bimg;
        if (np >= NPLANE) { np -= NPLANE; nbimg++; }
        float4 nr4, ng4, nb4;
        if (has_next) {
            const float* nxb = x + (size_t)nbimg * 3 * NPLANE + np;
            nr4 = *(const float4*)(nxb);
            ng4 = *(const float4*)(nxb + NPLANE);
            nb4 = *(const float4*)(nxb + 2 * NPLANE);
        }

        // Phase 4: unpack + lerp + store.
        float o[4];
        #pragma unroll
        for (int k = 0; k < 4; k++) {
            float2 f00 = __half22float2(*(const __half2*)&w[4*k + 0]);
            float2 f01 = __half22float2(*(const __half2*)&w[4*k + 1]);
            float2 f10 = __half22float2(*(const __half2*)&w[4*k + 2]);
            float2 f11 = __half22float2(*(const __half2*)&w[4*k + 3]);
            float c00 = fmaf(rd[k], f00.y - f00.x, f00.x);
            float c01 = fmaf(rd[k], f01.y - f01.x, f01.x);
            float c10 = fmaf(rd[k], f10.y - f10.x, f10.x);
            float c11 = fmaf(rd[k], f11.y - f11.x, f11.x);
            float c0  = fmaf(gd[k], c01 - c00, c00);
            float c1  = fmaf(gd[k], c11 - c10, c10);
            o[k] = fmaf(bd[k], c1 - c0, c0);
        }
        *(float4*)(outc + (size_t)bimg * 3 * NPLANE + p)
            = make_float4(o[0], o[1], o[2], o[3]);

        if (!has_next) break;
        gidx = ngidx; bimg = nbimg; p = np;
        r4 = nr4; g4 = ng4; b4 = nb4;
    }
}

extern "C" void kernel_launch(void* const* d_in, const int* in_sizes, int n_in,
                              void* d_out, int out_size) {
    const float* lut = (const float*)d_in[0];
    const float* x   = (const float*)d_in[1];
    float* out       = (float*)d_out;

    cudaFuncSetAttribute(lut3d_kernel,
                         cudaFuncAttributeMaxDynamicSharedMemorySize,
                         SMEM_BYTES);
    lut3d_kernel<<<NCTA, THREADS, SMEM_BYTES>>>(lut, x, out);
}